// round 1
// baseline (speedup 1.0000x reference)
#include <cuda_runtime.h>
#include <cstdint>
#include <cstddef>

// ---------------------------------------------------------------------------
// FuseLayer: out_i = sum_j relu(adj_i @ (x_ij @ W_ij) + b_ij)
// Levels: N = {8000, 4000, 2000}, DIM=128, row offsets {0, 8000, 12000}.
// Pipeline: zero X -> build X (gather/scatter) -> Y = X@W (tf32 mma)
//           -> ZR = relu(adj@Y + b) (tf32 mma) -> out = fold3(ZR)
// ---------------------------------------------------------------------------

#define TOTROWS 14000
#define XCOLS   384

__device__ float g_X [TOTROWS * XCOLS];
__device__ float g_Y [TOTROWS * XCOLS];
__device__ float g_ZR[TOTROWS * XCOLS];

// ------------------------------- helpers -----------------------------------

__device__ __forceinline__ uint32_t cvt_tf32(float f) {
    uint32_t r;
    asm("cvt.rna.tf32.f32 %0, %1;" : "=r"(r) : "f"(f));
    return r;
}
__device__ __forceinline__ uint32_t smem_u32(const void* p) {
    return (uint32_t)__cvta_generic_to_shared(p);
}
__device__ __forceinline__ void cp_async16(uint32_t dst, const void* src) {
    asm volatile("cp.async.cg.shared.global [%0], [%1], 16;\n"
                 :: "r"(dst), "l"(src));
}
__device__ __forceinline__ void cp_commit() {
    asm volatile("cp.async.commit_group;\n");
}
__device__ __forceinline__ void cp_wait0() {
    asm volatile("cp.async.wait_group 0;\n");
}
__device__ __forceinline__ void mma_tf32(float* c, const uint32_t* a, const uint32_t* b) {
    asm volatile(
        "mma.sync.aligned.m16n8k8.row.col.f32.tf32.tf32.f32 "
        "{%0,%1,%2,%3}, {%4,%5,%6,%7}, {%8,%9}, {%0,%1,%2,%3};\n"
        : "+f"(c[0]), "+f"(c[1]), "+f"(c[2]), "+f"(c[3])
        : "r"(a[0]), "r"(a[1]), "r"(a[2]), "r"(a[3]),
          "r"(b[0]), "r"(b[1]));
}

// ------------------------------- GEMM core ---------------------------------
// C[M x 128block] = A[M x K] @ B[K x 128block]; BM=128 BN=128 BK=16,
// 256 threads = 8 warps (2 x 4), warp tile 64x32, m16n8k8 tf32.

#define BM 128
#define BN 128
#define BK 16
#define PADA 20    // As row stride (floats): conflict-light, 16B-aligned
#define PADB 132   // Bs row stride

struct GemmSmem {
    float As[2][BM * PADA];   // 2*128*20*4  = 20480 B
    float Bs[2][BK * PADB];   // 2*16*132*4  = 16896 B
};

template<bool RELU>
__device__ __forceinline__ void gemm_tile(
    const float* __restrict__ A, int lda,
    const float* __restrict__ B, int ldb,
    float* __restrict__ C, int ldc,
    int M, int K, int mblock, const float* __restrict__ bias)
{
    __shared__ GemmSmem sm;
    const int tid  = threadIdx.x;
    const int lane = tid & 31, wid = tid >> 5;
    const int warpM = wid >> 2, warpN = wid & 3;       // 2 x 4 warps
    const int g = lane >> 2, tg = lane & 3;
    const int m0 = mblock * BM;

    float acc[4][4][4];
    #pragma unroll
    for (int a = 0; a < 4; ++a)
        #pragma unroll
        for (int b = 0; b < 4; ++b)
            #pragma unroll
            for (int c = 0; c < 4; ++c) acc[a][b][c] = 0.f;

    auto loadStage = [&](int kt, int s) {
        const int kbase = kt * BK;
        // A tile: 128 rows x 16 cols = 512 float4, 2 per thread.
        #pragma unroll
        for (int t = 0; t < 2; ++t) {
            int c  = tid + t * 256;
            int ar = c >> 2, aq = c & 3;
            int arow = m0 + ar;
            if (arow >= M) arow = M - 1;   // clamp: OOB rows never stored
            const float* gsrc = A + (size_t)arow * lda + kbase + aq * 4;
            cp_async16(smem_u32(&sm.As[s][ar * PADA + aq * 4]), gsrc);
        }
        // B tile: 16 rows x 128 cols = 512 float4, 2 per thread. Always in range.
        #pragma unroll
        for (int t = 0; t < 2; ++t) {
            int c  = tid + t * 256;
            int br = c >> 5, bc = (c & 31) * 4;
            const float* gsrc = B + (size_t)(kbase + br) * ldb + bc;
            cp_async16(smem_u32(&sm.Bs[s][br * PADB + bc]), gsrc);
        }
    };

    const int KT = K / BK;   // K is always a multiple of 16 here
    loadStage(0, 0);
    cp_commit();

    for (int kt = 0; kt < KT; ++kt) {
        cp_wait0();
        __syncthreads();
        if (kt + 1 < KT) loadStage(kt + 1, (kt + 1) & 1);
        cp_commit();

        const int s = kt & 1;
        const float* As = sm.As[s];
        const float* Bs = sm.Bs[s];
        #pragma unroll
        for (int kk = 0; kk < BK; kk += 8) {
            uint32_t afr[4][4], bfr[4][2];
            #pragma unroll
            for (int mf = 0; mf < 4; ++mf) {
                int r0 = warpM * 64 + mf * 16 + g;
                afr[mf][0] = cvt_tf32(As[(r0    ) * PADA + kk + tg    ]);
                afr[mf][1] = cvt_tf32(As[(r0 + 8) * PADA + kk + tg    ]);
                afr[mf][2] = cvt_tf32(As[(r0    ) * PADA + kk + tg + 4]);
                afr[mf][3] = cvt_tf32(As[(r0 + 8) * PADA + kk + tg + 4]);
            }
            #pragma unroll
            for (int nf = 0; nf < 4; ++nf) {
                int c0 = warpN * 32 + nf * 8 + g;
                bfr[nf][0] = cvt_tf32(Bs[(kk + tg    ) * PADB + c0]);
                bfr[nf][1] = cvt_tf32(Bs[(kk + tg + 4) * PADB + c0]);
            }
            #pragma unroll
            for (int mf = 0; mf < 4; ++mf)
                #pragma unroll
                for (int nf = 0; nf < 4; ++nf)
                    mma_tf32(acc[mf][nf], afr[mf], bfr[nf]);
        }
    }

    // epilogue
    #pragma unroll
    for (int mf = 0; mf < 4; ++mf) {
        int rbase = m0 + warpM * 64 + mf * 16 + g;
        #pragma unroll
        for (int nf = 0; nf < 4; ++nf) {
            int cbase = warpN * 32 + nf * 8 + tg * 2;
            #pragma unroll
            for (int rr = 0; rr < 2; ++rr) {
                int row = rbase + rr * 8;
                if (row < M) {
                    #pragma unroll
                    for (int cc = 0; cc < 2; ++cc) {
                        float v = acc[mf][nf][rr * 2 + cc];
                        int col = cbase + cc;
                        if (RELU) v = fmaxf(v + bias[col], 0.f);
                        C[(size_t)row * ldc + col] = v;
                    }
                }
            }
        }
    }
}

// ------------------------------- kernels -----------------------------------

__device__ __forceinline__ int levelM(int level)   { return level == 0 ? 8000 : (level == 1 ? 4000 : 2000); }
__device__ __forceinline__ int levelOff(int level) { return level == 0 ? 0    : (level == 1 ? 8000 : 12000); }

__global__ void zero_x_kernel() {
    size_t i = (size_t)blockIdx.x * 1024 + threadIdx.x;   // grid 5250*1024 == 14000*384
    g_X[i] = 0.f;
}

__global__ void build_x_kernel(const float* __restrict__ h0,
                               const float* __restrict__ h1,
                               const float* __restrict__ h2,
                               const int* __restrict__ idx0,
                               const int* __restrict__ idx1) {
    int b = blockIdx.x, d = threadIdx.x;   // 128 threads: one feature each
    float v; size_t dst;
    if (b < 8000)       {                      v = h0[(size_t)b * 128 + d];                 dst = (size_t)b * 384 + d; }
    else if (b < 12000) { int r = b - 8000;    v = h1[(size_t)r * 128 + d];                 dst = (size_t)idx0[r] * 384 + 128 + d; }
    else if (b < 14000) { int r = b - 12000;   v = h2[(size_t)r * 128 + d];                 dst = (size_t)idx0[idx1[r]] * 384 + 256 + d; }
    else if (b < 18000) { int r = b - 14000;   v = h0[(size_t)idx0[r] * 128 + d];           dst = (size_t)(8000 + r) * 384 + d; }
    else if (b < 22000) { int r = b - 18000;   v = h1[(size_t)r * 128 + d];                 dst = (size_t)(8000 + r) * 384 + 128 + d; }
    else if (b < 24000) { int r = b - 22000;   v = h2[(size_t)r * 128 + d];                 dst = (size_t)(8000 + idx1[r]) * 384 + 256 + d; }
    else if (b < 26000) { int r = b - 24000;   v = h0[(size_t)idx0[idx1[r]] * 128 + d];     dst = (size_t)(12000 + r) * 384 + d; }
    else if (b < 28000) { int r = b - 26000;   v = h1[(size_t)idx1[r] * 128 + d];           dst = (size_t)(12000 + r) * 384 + 128 + d; }
    else                { int r = b - 28000;   v = h2[(size_t)r * 128 + d];                 dst = (size_t)(12000 + r) * 384 + 256 + d; }
    g_X[dst] = v;
}

// Y_i[:, j*128:(j+1)*128] = X_i[:, j*128:(j+1)*128] @ W[i][j]
__global__ __launch_bounds__(256, 2)
void gemm_xw_kernel(const float* __restrict__ Ws) {
    const int level = blockIdx.z, j = blockIdx.y;
    const int M = levelM(level);
    if ((int)blockIdx.x * BM >= M) return;
    const int ro = levelOff(level);
    const float* A = g_X + (size_t)ro * 384 + j * 128;
    const float* B = Ws + (size_t)(level * 3 + j) * 128 * 128;
    float*       C = g_Y + (size_t)ro * 384 + j * 128;
    gemm_tile<false>(A, 384, B, 128, C, 384, M, 128, blockIdx.x, nullptr);
}

// ZR_i[:, j*128:(j+1)*128] = relu(adj_i @ Y_i[:, jblock] + b[i][j])
__global__ __launch_bounds__(256, 2)
void gemm_adj_kernel(const float* __restrict__ adj0,
                     const float* __restrict__ adj1,
                     const float* __restrict__ adj2,
                     const float* __restrict__ bs) {
    const int level = blockIdx.z, j = blockIdx.y;
    const int M = levelM(level);
    if ((int)blockIdx.x * BM >= M) return;
    const int ro = levelOff(level);
    const float* A = (level == 0) ? adj0 : (level == 1) ? adj1 : adj2;
    const float* B = g_Y  + (size_t)ro * 384 + j * 128;
    float*       C = g_ZR + (size_t)ro * 384 + j * 128;
    const float* bias = bs + (size_t)(level * 3 + j) * 128;
    gemm_tile<true>(A, M, B, 384, C, 384, M, M, blockIdx.x, bias);
}

// out[r,d] = ZR[r,d] + ZR[r,128+d] + ZR[r,256+d]  (relu+bias already applied)
__global__ void reduce_kernel(float* __restrict__ out) {
    int r = blockIdx.x, d = threadIdx.x;
    const float* z = g_ZR + (size_t)r * 384;
    out[(size_t)r * 128 + d] = z[d] + z[128 + d] + z[256 + d];
}

// ------------------------------- launch ------------------------------------

extern "C" void kernel_launch(void* const* d_in, const int* in_sizes, int n_in,
                              void* d_out, int out_size) {
    const float* adj0 = (const float*)d_in[0];
    const float* adj1 = (const float*)d_in[1];
    const float* adj2 = (const float*)d_in[2];
    const float* h0   = (const float*)d_in[3];
    const float* h1   = (const float*)d_in[4];
    const float* h2   = (const float*)d_in[5];
    const int*   idx0 = (const int*)  d_in[6];
    const int*   idx1 = (const int*)  d_in[7];
    const float* Ws   = (const float*)d_in[8];
    const float* bs   = (const float*)d_in[9];
    float* out = (float*)d_out;

    zero_x_kernel <<<5250, 1024>>>();
    build_x_kernel<<<30000, 128>>>(h0, h1, h2, idx0, idx1);
    gemm_xw_kernel <<<dim3(63, 3, 3), 256>>>(Ws);
    gemm_adj_kernel<<<dim3(63, 3, 3), 256>>>(adj0, adj1, adj2, bs);
    reduce_kernel <<<14000, 128>>>(out);
    (void)in_sizes; (void)n_in; (void)out_size;
}

// round 5
// speedup vs baseline: 1.8076x; 1.8076x over previous
#include <cuda_runtime.h>
#include <cuda_fp16.h>
#include <cstdint>
#include <cstddef>

// ---------------------------------------------------------------------------
// FuseLayer: out_i = sum_j relu(adj_i @ (x_ij @ W_ij) + b_ij)
// N = {8000, 4000, 2000}, DIM=128, row offsets {0, 8000, 12000}.
// Pipeline (portable sm_80-class ISA only — ptxas targets sm_103 non-'a'):
//   convert adj -> fp16 (x1024 exact scale)
//   zero X -> build X (gather/scatter)
//   Y = X @ W  (legacy tf32 mma), stored fp16 row-major
//   ZR = relu((adj16 @ Y16) * 2^-10 + b)  (fp16 m16n8k16 mma + ldmatrix)
//   out = fold3(ZR)
// ---------------------------------------------------------------------------

#define TOTROWS 14000

__device__ float  g_X [TOTROWS * 384];
__device__ float  g_ZR[TOTROWS * 384];
__device__ __half g_Yh[TOTROWS * 384];
__device__ __half g_adjh0[64000000];
__device__ __half g_adjh1[16000000];
__device__ __half g_adjh2[ 4000000];

// ------------------------------- helpers -----------------------------------

__device__ __forceinline__ uint32_t cvt_tf32(float f) {
    uint32_t r;
    asm("cvt.rna.tf32.f32 %0, %1;" : "=r"(r) : "f"(f));
    return r;
}
__device__ __forceinline__ uint32_t smem_u32(const void* p) {
    return (uint32_t)__cvta_generic_to_shared(p);
}
__device__ __forceinline__ void cp_async16(uint32_t dst, const void* src) {
    asm volatile("cp.async.cg.shared.global [%0], [%1], 16;\n" :: "r"(dst), "l"(src));
}
__device__ __forceinline__ void cp_async16_pred(uint32_t dst, const void* src, bool full) {
    int sz = full ? 16 : 0;
    asm volatile("cp.async.cg.shared.global [%0], [%1], 16, %2;\n"
                 :: "r"(dst), "l"(src), "r"(sz));
}
__device__ __forceinline__ void cp_commit() {
    asm volatile("cp.async.commit_group;\n");
}
template<int N>
__device__ __forceinline__ void cp_wait() {
    asm volatile("cp.async.wait_group %0;\n" :: "n"(N));
}
__device__ __forceinline__ void ldm_x4(uint32_t* r, uint32_t addr) {
    asm volatile("ldmatrix.sync.aligned.m8n8.x4.shared.b16 {%0,%1,%2,%3}, [%4];"
                 : "=r"(r[0]), "=r"(r[1]), "=r"(r[2]), "=r"(r[3]) : "r"(addr));
}
__device__ __forceinline__ void ldm_x4_t(uint32_t* r, uint32_t addr) {
    asm volatile("ldmatrix.sync.aligned.m8n8.x4.trans.shared.b16 {%0,%1,%2,%3}, [%4];"
                 : "=r"(r[0]), "=r"(r[1]), "=r"(r[2]), "=r"(r[3]) : "r"(addr));
}
__device__ __forceinline__ void mma_fp16(float* c, const uint32_t* a, const uint32_t* b) {
    asm volatile(
        "mma.sync.aligned.m16n8k16.row.col.f32.f16.f16.f32 "
        "{%0,%1,%2,%3}, {%4,%5,%6,%7}, {%8,%9}, {%0,%1,%2,%3};\n"
        : "+f"(c[0]), "+f"(c[1]), "+f"(c[2]), "+f"(c[3])
        : "r"(a[0]), "r"(a[1]), "r"(a[2]), "r"(a[3]), "r"(b[0]), "r"(b[1]));
}
__device__ __forceinline__ void mma_tf32(float* c, const uint32_t* a, const uint32_t* b) {
    asm volatile(
        "mma.sync.aligned.m16n8k8.row.col.f32.tf32.tf32.f32 "
        "{%0,%1,%2,%3}, {%4,%5,%6,%7}, {%8,%9}, {%0,%1,%2,%3};\n"
        : "+f"(c[0]), "+f"(c[1]), "+f"(c[2]), "+f"(c[3])
        : "r"(a[0]), "r"(a[1]), "r"(a[2]), "r"(a[3]), "r"(b[0]), "r"(b[1]));
}

__device__ __forceinline__ int levelM(int level)   { return level == 0 ? 8000 : (level == 1 ? 4000 : 2000); }
__device__ __forceinline__ int levelOff(int level) { return level == 0 ? 0    : (level == 1 ? 8000 : 12000); }

// ------------------------- adj f32 -> fp16 (x1024) --------------------------

__global__ void convert_adj_kernel(const float* __restrict__ src, int which, int n8) {
    int i = blockIdx.x * 256 + threadIdx.x;
    if (i >= n8) return;
    __half* dst = (which == 0) ? g_adjh0 : (which == 1) ? g_adjh1 : g_adjh2;
    const float4* s = reinterpret_cast<const float4*>(src) + (size_t)i * 2;
    float4 a = s[0], b = s[1];
    const float S = 1024.f;   // exact power of two; undone in epilogue
    __half2 h0 = __floats2half2_rn(a.x * S, a.y * S);
    __half2 h1 = __floats2half2_rn(a.z * S, a.w * S);
    __half2 h2 = __floats2half2_rn(b.x * S, b.y * S);
    __half2 h3 = __floats2half2_rn(b.z * S, b.w * S);
    uint4 o;
    o.x = *reinterpret_cast<uint32_t*>(&h0);
    o.y = *reinterpret_cast<uint32_t*>(&h1);
    o.z = *reinterpret_cast<uint32_t*>(&h2);
    o.w = *reinterpret_cast<uint32_t*>(&h3);
    reinterpret_cast<uint4*>(dst)[i] = o;
}

// ------------------------- X build (gather/scatter) ------------------------

__global__ void zero_x_kernel() {
    size_t i = (size_t)blockIdx.x * 1024 + threadIdx.x;   // 5250*1024 == 14000*384
    g_X[i] = 0.f;
}

__global__ void build_x_kernel(const float* __restrict__ h0,
                               const float* __restrict__ h1,
                               const float* __restrict__ h2,
                               const int* __restrict__ idx0,
                               const int* __restrict__ idx1) {
    int b = blockIdx.x, d = threadIdx.x;
    float v; size_t dst;
    if (b < 8000)       {                      v = h0[(size_t)b * 128 + d];                 dst = (size_t)b * 384 + d; }
    else if (b < 12000) { int r = b - 8000;    v = h1[(size_t)r * 128 + d];                 dst = (size_t)idx0[r] * 384 + 128 + d; }
    else if (b < 14000) { int r = b - 12000;   v = h2[(size_t)r * 128 + d];                 dst = (size_t)idx0[idx1[r]] * 384 + 256 + d; }
    else if (b < 18000) { int r = b - 14000;   v = h0[(size_t)idx0[r] * 128 + d];           dst = (size_t)(8000 + r) * 384 + d; }
    else if (b < 22000) { int r = b - 18000;   v = h1[(size_t)r * 128 + d];                 dst = (size_t)(8000 + r) * 384 + 128 + d; }
    else if (b < 24000) { int r = b - 22000;   v = h2[(size_t)r * 128 + d];                 dst = (size_t)(8000 + idx1[r]) * 384 + 256 + d; }
    else if (b < 26000) { int r = b - 24000;   v = h0[(size_t)idx0[idx1[r]] * 128 + d];     dst = (size_t)(12000 + r) * 384 + d; }
    else if (b < 28000) { int r = b - 26000;   v = h1[(size_t)idx1[r] * 128 + d];           dst = (size_t)(12000 + r) * 384 + 128 + d; }
    else                { int r = b - 28000;   v = h2[(size_t)r * 128 + d];                 dst = (size_t)(12000 + r) * 384 + 256 + d; }
    g_X[dst] = v;
}

// ---------------- tf32 GEMM: Yh = fp16(X @ W), row-major -------------------

#define XW_BM 128
#define XW_BK 16
#define XW_PADA 20
#define XW_PADB 132

struct XwSmem {
    float As[2][XW_BM * XW_PADA];
    float Bs[2][XW_BK * XW_PADB];
};

__global__ __launch_bounds__(256, 2)
void gemm_xw_kernel(const float* __restrict__ Ws) {
    const int level = blockIdx.z, j = blockIdx.y;
    const int M = levelM(level);
    if ((int)blockIdx.x * XW_BM >= M) return;
    const int ro = levelOff(level);
    const float* A = g_X + (size_t)ro * 384 + j * 128;          // lda=384
    const float* B = Ws + (size_t)(level * 3 + j) * 128 * 128;  // ldb=128

    __shared__ XwSmem sm;
    const int tid  = threadIdx.x;
    const int lane = tid & 31, wid = tid >> 5;
    const int warpM = wid >> 2, warpN = wid & 3;
    const int g = lane >> 2, tg = lane & 3;
    const int m0 = blockIdx.x * XW_BM;

    float acc[4][4][4];
    #pragma unroll
    for (int a = 0; a < 4; ++a)
        #pragma unroll
        for (int b = 0; b < 4; ++b)
            #pragma unroll
            for (int c = 0; c < 4; ++c) acc[a][b][c] = 0.f;

    auto loadStage = [&](int kt, int s) {
        const int kbase = kt * XW_BK;
        #pragma unroll
        for (int t = 0; t < 2; ++t) {
            int c  = tid + t * 256;
            int ar = c >> 2, aq = c & 3;
            int arow = m0 + ar;
            if (arow >= M) arow = M - 1;
            cp_async16(smem_u32(&sm.As[s][ar * XW_PADA + aq * 4]),
                       A + (size_t)arow * 384 + kbase + aq * 4);
        }
        #pragma unroll
        for (int t = 0; t < 2; ++t) {
            int c  = tid + t * 256;
            int br = c >> 5, bc = (c & 31) * 4;
            cp_async16(smem_u32(&sm.Bs[s][br * XW_PADB + bc]),
                       B + (size_t)(kbase + br) * 128 + bc);
        }
    };

    loadStage(0, 0);
    cp_commit();

    for (int kt = 0; kt < 8; ++kt) {   // K=128
        cp_wait<0>();
        __syncthreads();
        if (kt + 1 < 8) loadStage(kt + 1, (kt + 1) & 1);
        cp_commit();

        const int s = kt & 1;
        const float* As = sm.As[s];
        const float* Bs = sm.Bs[s];
        #pragma unroll
        for (int kk = 0; kk < XW_BK; kk += 8) {
            uint32_t afr[4][4], bfr[4][2];
            #pragma unroll
            for (int mf = 0; mf < 4; ++mf) {
                int r0 = warpM * 64 + mf * 16 + g;
                afr[mf][0] = cvt_tf32(As[(r0    ) * XW_PADA + kk + tg    ]);
                afr[mf][1] = cvt_tf32(As[(r0 + 8) * XW_PADA + kk + tg    ]);
                afr[mf][2] = cvt_tf32(As[(r0    ) * XW_PADA + kk + tg + 4]);
                afr[mf][3] = cvt_tf32(As[(r0 + 8) * XW_PADA + kk + tg + 4]);
            }
            #pragma unroll
            for (int nf = 0; nf < 4; ++nf) {
                int c0 = warpN * 32 + nf * 8 + g;
                bfr[nf][0] = cvt_tf32(Bs[(kk + tg    ) * XW_PADB + c0]);
                bfr[nf][1] = cvt_tf32(Bs[(kk + tg + 4) * XW_PADB + c0]);
            }
            #pragma unroll
            for (int mf = 0; mf < 4; ++mf)
                #pragma unroll
                for (int nf = 0; nf < 4; ++nf)
                    mma_tf32(acc[mf][nf], afr[mf], bfr[nf]);
        }
        __syncthreads();
    }

    // store fp16 row-major into Yh[:, j*128 + ...]
    #pragma unroll
    for (int mf = 0; mf < 4; ++mf) {
        int rbase = m0 + warpM * 64 + mf * 16 + g;
        #pragma unroll
        for (int nf = 0; nf < 4; ++nf) {
            int cbase = warpN * 32 + nf * 8 + tg * 2;
            #pragma unroll
            for (int rr = 0; rr < 2; ++rr) {
                int row = rbase + rr * 8;
                if (row < M) {
                    __half2 hv = __floats2half2_rn(acc[mf][nf][rr * 2],
                                                   acc[mf][nf][rr * 2 + 1]);
                    *reinterpret_cast<__half2*>(
                        &g_Yh[(size_t)(ro + row) * 384 + j * 128 + cbase]) = hv;
                }
            }
        }
    }
}

// ---------------- fp16 adj GEMM: ZR = relu(adj@Y * 2^-10 + b) --------------
// CTA 128x128 tile, 8 warps (2x4), warp 64x32, BK=32, ldmatrix + m16n8k16.
// 5 smem slots, 3 cp.async groups in flight, one syncthreads per iter.

#define NSLOT    5
#define A_STRIDE 80      // bytes per A row (32 halfs + 16B pad): conflict-free ldmatrix
#define B_STRIDE 272     // bytes per B row (128 halfs + 16B pad)
#define A_SLOT   (128 * A_STRIDE)            // 10240
#define B_SLOT   (32 * B_STRIDE)             // 8704
#define SLOT_B   (A_SLOT + B_SLOT)           // 18944
#define ADJ_SMEM (NSLOT * SLOT_B)            // 94720

__global__ __launch_bounds__(256, 2)
void adj_fp16_kernel(const float* __restrict__ bs) {
    const int j = blockIdx.x, mt = blockIdx.y, level = blockIdx.z;
    const int Mlev = levelM(level), ro = levelOff(level);
    if (mt * 128 >= Mlev) return;
    const int m0 = mt * 128;
    const __half* A = (level == 0) ? g_adjh0 : (level == 1) ? g_adjh1 : g_adjh2;
    const __half* B = g_Yh + (size_t)ro * 384 + j * 128;
    const int KT = (Mlev + 31) >> 5;   // 250 / 125 / 63

    extern __shared__ char sm[];
    const int tid = threadIdx.x, lane = tid & 31, wid = tid >> 5;
    const int warpM = wid >> 2, warpN = wid & 3;   // 2 x 4

    float acc[4][4][4];
    #pragma unroll
    for (int a = 0; a < 4; ++a)
        #pragma unroll
        for (int b = 0; b < 4; ++b)
            #pragma unroll
            for (int c = 0; c < 4; ++c) acc[a][b][c] = 0.f;

    auto load_stage = [&](int chunk, int slot) {
        const int k0 = chunk * 32;
        char* base = sm + slot * SLOT_B;
        // A: 128 rows x 64B data (4 x 16B chunks), 2 per thread
        #pragma unroll
        for (int t = 0; t < 2; ++t) {
            int c = tid + t * 256;
            int r = c >> 2, ch = c & 3;
            int gm = m0 + r, gk = k0 + ch * 8;
            bool ok = (gm < Mlev) && (gk < Mlev);
            const __half* src = ok ? (A + (size_t)gm * Mlev + gk) : A;
            cp_async16_pred(smem_u32(base + r * A_STRIDE + ch * 16), src, ok);
        }
        // B: 32 rows x 256B data (16 x 16B chunks), 2 per thread
        #pragma unroll
        for (int t = 0; t < 2; ++t) {
            int c = tid + t * 256;
            int r = c >> 4, ch = c & 15;
            int gk = k0 + r;
            bool ok = gk < Mlev;
            const __half* src = ok ? (B + (size_t)gk * 384 + ch * 8) : B;
            cp_async16_pred(smem_u32(base + A_SLOT + r * B_STRIDE + ch * 16), src, ok);
        }
        cp_commit();
    };

    // prologue: 3 groups in flight (KT >= 63 always)
    load_stage(0, 0);
    load_stage(1, 1);
    load_stage(2, 2);

    const int rowA  = warpM * 64 + (lane & 15);
    const int hi    = lane >> 4;
    const int rowB  = lane & 15;

    for (int i = 0; i < KT; ++i) {
        cp_wait<2>();
        __syncthreads();
        if (i + 3 < KT) load_stage(i + 3, (i + 3) % NSLOT);
        else            cp_commit();   // keep group bookkeeping uniform

        const uint32_t aBase = smem_u32(sm + (i % NSLOT) * SLOT_B);
        const uint32_t bBase = aBase + A_SLOT;

        #pragma unroll
        for (int kk = 0; kk < 32; kk += 16) {
            uint32_t afr[4][4], bfr[2][4];
            #pragma unroll
            for (int mf = 0; mf < 4; ++mf)
                ldm_x4(afr[mf], aBase + (rowA + mf * 16) * A_STRIDE
                                      + ((kk >> 3) + hi) * 16);
            #pragma unroll
            for (int nb = 0; nb < 2; ++nb) {
                int col = warpN * 32 + nb * 16 + hi * 8;
                ldm_x4_t(bfr[nb], bBase + (kk + rowB) * B_STRIDE + col * 2);
            }
            #pragma unroll
            for (int mf = 0; mf < 4; ++mf)
                #pragma unroll
                for (int nb = 0; nb < 2; ++nb) {
                    mma_fp16(acc[mf][nb * 2    ], afr[mf], &bfr[nb][0]);
                    mma_fp16(acc[mf][nb * 2 + 1], afr[mf], &bfr[nb][2]);
                }
        }
    }

    // epilogue: undo 2^10 adj scale, add bias, relu, store to ZR
    const float S = 1.f / 1024.f;
    const float* biasp = bs + (size_t)(level * 3 + j) * 128;
    const int rbase = m0 + warpM * 64 + (lane >> 2);
    #pragma unroll
    for (int nf = 0; nf < 4; ++nf) {
        int c0 = warpN * 32 + nf * 8 + (lane & 3) * 2;
        float b0 = __ldg(biasp + c0), b1 = __ldg(biasp + c0 + 1);
        #pragma unroll
        for (int mf = 0; mf < 4; ++mf) {
            int r0 = rbase + mf * 16;
            if (r0 < Mlev) {
                float2 v = make_float2(fmaxf(acc[mf][nf][0] * S + b0, 0.f),
                                       fmaxf(acc[mf][nf][1] * S + b1, 0.f));
                *reinterpret_cast<float2*>(
                    &g_ZR[(size_t)(ro + r0) * 384 + j * 128 + c0]) = v;
            }
            int r1 = r0 + 8;
            if (r1 < Mlev) {
                float2 v = make_float2(fmaxf(acc[mf][nf][2] * S + b0, 0.f),
                                       fmaxf(acc[mf][nf][3] * S + b1, 0.f));
                *reinterpret_cast<float2*>(
                    &g_ZR[(size_t)(ro + r1) * 384 + j * 128 + c0]) = v;
            }
        }
    }
}

// out[r,d] = ZR[r,d] + ZR[r,128+d] + ZR[r,256+d]
__global__ void reduce_kernel(float* __restrict__ out) {
    int r = blockIdx.x, d = threadIdx.x;
    const float* z = g_ZR + (size_t)r * 384;
    out[(size_t)r * 128 + d] = z[d] + z[128 + d] + z[256 + d];
}

// ------------------------------- launch ------------------------------------

extern "C" void kernel_launch(void* const* d_in, const int* in_sizes, int n_in,
                              void* d_out, int out_size) {
    const float* adj0 = (const float*)d_in[0];
    const float* adj1 = (const float*)d_in[1];
    const float* adj2 = (const float*)d_in[2];
    const float* h0   = (const float*)d_in[3];
    const float* h1   = (const float*)d_in[4];
    const float* h2   = (const float*)d_in[5];
    const int*   idx0 = (const int*)  d_in[6];
    const int*   idx1 = (const int*)  d_in[7];
    const float* Ws   = (const float*)d_in[8];
    const float* bs   = (const float*)d_in[9];
    float* out = (float*)d_out;

    // Unconditional (no static guards): idempotent, enqueues nothing.
    cudaFuncSetAttribute(adj_fp16_kernel,
                         cudaFuncAttributeMaxDynamicSharedMemorySize, ADJ_SMEM);

    convert_adj_kernel<<<31250, 256>>>(adj0, 0, 8000000);
    convert_adj_kernel<<< 7813, 256>>>(adj1, 1, 2000000);
    convert_adj_kernel<<< 1954, 256>>>(adj2, 2,  500000);
    zero_x_kernel <<<5250, 1024>>>();
    build_x_kernel<<<30000, 128>>>(h0, h1, h2, idx0, idx1);
    gemm_xw_kernel<<<dim3(63, 3, 3), 256>>>(Ws);
    adj_fp16_kernel<<<dim3(3, 63, 3), 256, ADJ_SMEM>>>(bs);
    reduce_kernel <<<14000, 128>>>(out);
    (void)in_sizes; (void)n_in; (void)out_size;
}